// round 12
// baseline (speedup 1.0000x reference)
#include <cuda_runtime.h>
#include <cuda_bf16.h>
#include <cstdint>

#define BB 64
#define NP 1024
#define LL 64
#define HH 128
#define W1K 67
#define TN 128
#define NT (BB * 8)       // 512 tiles of 128 points
#define MLP_GRID 148
#define KS 136            // bf16 elements per row (272B, 16B-aligned stride)
#define H2ROW 132         // fp32 row stride for h2

__device__ float g_acc[3];
__device__ float g_w1l[BB * HH];

__global__ void init_kernel() {
    if (threadIdx.x < 3) g_acc[threadIdx.x] = 0.0f;
}

__global__ void __launch_bounds__(128) w1l_kernel(
    const float* __restrict__ latent, const float* __restrict__ W1,
    const float* __restrict__ b1)
{
    __shared__ float slat[LL];
    const int b = blockIdx.x, o = threadIdx.x;
    if (o < LL) slat[o] = latent[b * LL + o];
    __syncthreads();
    float acc = b1[o];
    const float* wrow = W1 + o * W1K + 3;
    #pragma unroll 8
    for (int l = 0; l < LL; l++) acc = fmaf(wrow[l], slat[l], acc);
    g_w1l[b * HH + o] = acc;
}

__device__ __forceinline__ float block_sum(float v, float* scratch) {
    #pragma unroll
    for (int off = 16; off; off >>= 1) v += __shfl_down_sync(0xffffffffu, v, off);
    int lane = threadIdx.x & 31, w = threadIdx.x >> 5;
    if (lane == 0) scratch[w] = v;
    __syncthreads();
    int nw = blockDim.x >> 5;
    v = (threadIdx.x < nw) ? scratch[threadIdx.x] : 0.0f;
    if (w == 0) {
        #pragma unroll
        for (int off = 16; off; off >>= 1) v += __shfl_down_sync(0xffffffffu, v, off);
    }
    return v;
}

__device__ __forceinline__ uint32_t smem_u32(const void* p) {
    uint32_t a;
    asm("{ .reg .u64 t; cvta.to.shared.u64 t, %1; cvt.u32.u64 %0, t; }"
        : "=r"(a) : "l"(p));
    return a;
}
__device__ __forceinline__ void ldmx4(uint32_t* r, uint32_t addr) {
    asm volatile("ldmatrix.sync.aligned.m8n8.x4.shared.b16 {%0,%1,%2,%3}, [%4];"
                 : "=r"(r[0]), "=r"(r[1]), "=r"(r[2]), "=r"(r[3]) : "r"(addr));
}
__device__ __forceinline__ void mma_bf16(float* c, const uint32_t* a,
                                         const uint32_t* b) {
    asm volatile(
        "mma.sync.aligned.m16n8k16.row.col.f32.bf16.bf16.f32 "
        "{%0,%1,%2,%3}, {%4,%5,%6,%7}, {%8,%9}, {%0,%1,%2,%3};"
        : "+f"(c[0]), "+f"(c[1]), "+f"(c[2]), "+f"(c[3])
        : "r"(a[0]), "r"(a[1]), "r"(a[2]), "r"(a[3]), "r"(b[0]), "r"(b[1]));
}
__device__ __forceinline__ unsigned pack_bf2(__nv_bfloat16 a, __nv_bfloat16 b) {
    return (unsigned)__bfloat16_as_ushort(a) |
           ((unsigned)__bfloat16_as_ushort(b) << 16);
}

// SMEM byte offsets within dynamic region
#define OFF_W2HI 0
#define OFF_W2LO 34816
#define OFF_HHI  69632
#define OFF_HLO  104448
#define OFF_H2   69632          // overlays HHI/HLO (read-after-mma only)
#define OFF_MISC 139264

// ---------------------------------------------------------------------------
// Persistent MLP, split-bf16 mma.sync GEMM2. 148 CTAs x 256 thr, 512 tiles.
// ---------------------------------------------------------------------------
__global__ void __launch_bounds__(256) mlp_kernel(
    const float* __restrict__ pc, const float* __restrict__ pc_gt,
    const float* __restrict__ W2, const float* __restrict__ b2,
    const float* __restrict__ W1,
    const float* __restrict__ W3, const float* __restrict__ b3,
    float* __restrict__ out_est)
{
    extern __shared__ float smf[];
    char* sb = (char*)smf;
    __nv_bfloat16* w2hi = (__nv_bfloat16*)(sb + OFF_W2HI);  // [o][KS]
    __nv_bfloat16* w2lo = (__nv_bfloat16*)(sb + OFF_W2LO);
    __nv_bfloat16* hhi  = (__nv_bfloat16*)(sb + OFF_HHI);   // [n][KS]
    __nv_bfloat16* hlo  = (__nv_bfloat16*)(sb + OFF_HLO);
    float* s_h2 = (float*)(sb + OFF_H2);                    // [128][H2ROW]
    float* misc = (float*)(sb + OFF_MISC);
    float* swx  = misc;           // [3][128]
    float* swl  = swx + 384;      // 128
    float* sb2  = swl + 128;      // 128
    float* sw3  = sb2 + 128;      // 384
    float* sb3  = sw3 + 384;      // 4
    float* s_x  = sb3 + 4;        // [3][128]  pc tile
    float* s_g  = s_x + 384;      // [3][128]  pc_gt tile
    float* sred = s_g + 384;      // 8

    const int tid = threadIdx.x;
    const int lane = tid & 31;
    const int wid = tid >> 5;

    // ---- one-time stage: W2 hi/lo (bf16 split), small weights ----
    {
        const int o = tid & 127, kh = tid >> 7;
        const float* w2r = W2 + o * HH;
        for (int k = kh * 64; k < kh * 64 + 64; k += 2) {
            float w0 = w2r[k], w1 = w2r[k + 1];
            __nv_bfloat16 h0 = __float2bfloat16(w0);
            __nv_bfloat16 h1 = __float2bfloat16(w1);
            *(unsigned*)&w2hi[o * KS + k] = pack_bf2(h0, h1);
            *(unsigned*)&w2lo[o * KS + k] =
                pack_bf2(__float2bfloat16(w0 - __bfloat162float(h0)),
                         __float2bfloat16(w1 - __bfloat162float(h1)));
        }
    }
    for (int i = tid; i < 384; i += 256) {
        int k = i >> 7, o = i & 127;
        swx[k * 128 + o] = W1[o * W1K + k];
        sw3[i] = W3[i];
    }
    if (tid < 128) sb2[tid] = b2[tid];
    if (tid < 3) sb3[tid] = b3[tid];
    __syncthreads();

    const uint32_t u_w2hi = smem_u32(w2hi);
    const uint32_t u_w2lo = smem_u32(w2lo);
    const uint32_t u_hhi  = smem_u32(hhi);
    const uint32_t u_hlo  = smem_u32(hlo);

    // ldmatrix lane-address components (A: m16k16; B: n16k16 pair)
    const int lr = lane & 7;
    const int aq = lane >> 3;
    const int arow_off = ((aq & 1) << 3) + lr;
    const int acol_off = (aq >> 1) << 3;
    const int b4n = ((aq >> 1) << 3) + lr;   // n within pair
    const int b4k = (aq & 1) << 3;           // k half

    const int o0 = wid * 16;
    float l2acc = 0.0f;

    for (int t = blockIdx.x; t < NT; t += MLP_GRID) {
        const int b  = t >> 3;
        const int n0 = (t & 7) * TN;

        __syncthreads();   // prior tile epilogue reads of s_h2/s_x/s_g done
        for (int i = tid; i < 768; i += 256) {
            int r = i >> 7, n = i & 127;
            if (r < 3) s_x[r * 128 + n] = pc[(b * 3 + r) * NP + n0 + n];
            else       s_g[(r - 3) * 128 + n] = pc_gt[(b * 3 + r - 3) * NP + n0 + n];
        }
        if (tid < 128) swl[tid] = g_w1l[b * HH + tid];
        __syncthreads();

        // ---- layer 1 (fp32) -> split-bf16 h tiles [n][k] ----
        {
            const int n = tid & 127, kh = tid >> 7;
            const float x0 = s_x[n], x1 = s_x[128 + n], x2 = s_x[256 + n];
            #pragma unroll
            for (int k = kh * 64; k < kh * 64 + 64; k += 2) {
                float h0 = fmaxf(fmaf(swx[k], x0, fmaf(swx[128 + k], x1,
                             fmaf(swx[256 + k], x2, swl[k]))), 0.0f);
                float h1v = fmaxf(fmaf(swx[k + 1], x0, fmaf(swx[129 + k], x1,
                              fmaf(swx[257 + k], x2, swl[k + 1]))), 0.0f);
                __nv_bfloat16 bh0 = __float2bfloat16(h0);
                __nv_bfloat16 bh1 = __float2bfloat16(h1v);
                *(unsigned*)&hhi[n * KS + k] = pack_bf2(bh0, bh1);
                *(unsigned*)&hlo[n * KS + k] =
                    pack_bf2(__float2bfloat16(h0 - __bfloat162float(bh0)),
                             __float2bfloat16(h1v - __bfloat162float(bh1)));
            }
        }
        __syncthreads();

        // ---- GEMM2: warp o-strip [o0,o0+16), split-bf16 mma.sync ----
        float C[16][4];
        #pragma unroll
        for (int nt = 0; nt < 16; nt++)
            #pragma unroll
            for (int j = 0; j < 4; j++) C[nt][j] = 0.0f;

        #pragma unroll
        for (int k8 = 0; k8 < 8; k8++) {
            const int k0 = k8 * 16;
            const uint32_t aoff = (uint32_t)(o0 + arow_off) * 272u +
                                  (uint32_t)(k0 + acol_off) * 2u;
            uint32_t ah[4], al[4];
            ldmx4(ah, u_w2hi + aoff);
            ldmx4(al, u_w2lo + aoff);
            #pragma unroll
            for (int np = 0; np < 8; np++) {
                const uint32_t boff = (uint32_t)(np * 16 + b4n) * 272u +
                                      (uint32_t)(k0 + b4k) * 2u;
                uint32_t bh4[4], bl4[4];
                ldmx4(bh4, u_hhi + boff);
                ldmx4(bl4, u_hlo + boff);
                mma_bf16(C[2 * np],     ah, bh4);
                mma_bf16(C[2 * np + 1], ah, bh4 + 2);
                mma_bf16(C[2 * np],     ah, bl4);
                mma_bf16(C[2 * np + 1], ah, bl4 + 2);
                mma_bf16(C[2 * np],     al, bh4);
                mma_bf16(C[2 * np + 1], al, bh4 + 2);
            }
        }
        __syncthreads();   // all warps done reading h before s_h2 overlay

        // ---- bias + relu -> s_h2[o][n] ----
        {
            const int r = lane >> 2;
            const int cp = (lane & 3) * 2;
            const float bo  = sb2[o0 + r];
            const float bo8 = sb2[o0 + r + 8];
            #pragma unroll
            for (int nt = 0; nt < 16; nt++) {
                int n = nt * 8 + cp;
                s_h2[(o0 + r) * H2ROW + n]     = fmaxf(C[nt][0] + bo, 0.0f);
                s_h2[(o0 + r) * H2ROW + n + 1] = fmaxf(C[nt][1] + bo, 0.0f);
                s_h2[(o0 + r + 8) * H2ROW + n]     = fmaxf(C[nt][2] + bo8, 0.0f);
                s_h2[(o0 + r + 8) * H2ROW + n + 1] = fmaxf(C[nt][3] + bo8, 0.0f);
            }
        }
        __syncthreads();

        // ---- layer 3 (fp32, 3x128) on all 256 threads + epilogue ----
        {
            const int n3 = tid >> 1, kpar = tid & 1;
            float o0v = 0.0f, o1v = 0.0f, o2v = 0.0f;
            #pragma unroll 4
            for (int j = 0; j < 64; j++) {
                int k = 2 * j + kpar;
                float hv = s_h2[k * H2ROW + n3];
                o0v = fmaf(sw3[k], hv, o0v);
                o1v = fmaf(sw3[128 + k], hv, o1v);
                o2v = fmaf(sw3[256 + k], hv, o2v);
            }
            o0v += __shfl_xor_sync(0xffffffffu, o0v, 1);
            o1v += __shfl_xor_sync(0xffffffffu, o1v, 1);
            o2v += __shfl_xor_sync(0xffffffffu, o2v, 1);
            if (!kpar) {
                int base = (b * 3) * NP + n0 + n3;
                float e0 = s_x[n3]       - (o0v + sb3[0]);
                float e1 = s_x[128 + n3] - (o1v + sb3[1]);
                float e2 = s_x[256 + n3] - (o2v + sb3[2]);
                out_est[base] = e0;
                out_est[base + NP] = e1;
                out_est[base + 2 * NP] = e2;
                float d0 = s_g[n3] - e0;
                float d1 = s_g[128 + n3] - e1;
                float d2 = s_g[256 + n3] - e2;
                l2acc += fmaf(d0, d0, fmaf(d1, d1, d2 * d2));
            }
        }
    }

    __syncthreads();
    float s = block_sum(l2acc, sred);
    if (tid == 0) atomicAdd(&g_acc[2], s);
}

// ---------------------------------------------------------------------------
// Chamfer (unchanged from R8): 512 thr, 4 queries/thread, split m-scan.
// ---------------------------------------------------------------------------
__global__ void __launch_bounds__(512) chamfer_kernel(
    const float* __restrict__ pc_gt, const float* __restrict__ est)
{
    __shared__ float4 spts[NP];
    __shared__ float sup[256][4];
    __shared__ float sred[16];
    const int b = blockIdx.x;
    const int dir = blockIdx.y;
    const float* rows  = dir ? est   : pc_gt;
    const float* other = dir ? pc_gt : est;
    const int base = b * 3 * NP;
    const int tid  = threadIdx.x;
    const int qt   = tid & 255;
    const int half = tid >> 8;

    for (int i = tid; i < NP; i += 512) {
        float x = other[base + i];
        float y = other[base + NP + i];
        float z = other[base + 2 * NP + i];
        spts[i] = make_float4(x, y, z, fmaf(x, x, fmaf(y, y, z * z)));
    }
    __syncthreads();

    float qx[4], qy[4], qz[4], qa2[4];
    #pragma unroll
    for (int q = 0; q < 4; q++) {
        int n = qt + q * 256;
        float ax = rows[base + n];
        float ay = rows[base + NP + n];
        float az = rows[base + 2 * NP + n];
        qa2[q] = fmaf(ax, ax, fmaf(ay, ay, az * az));
        qx[q] = -2.0f * ax;
        qy[q] = -2.0f * ay;
        qz[q] = -2.0f * az;
    }

    float bst[4][2];
    #pragma unroll
    for (int q = 0; q < 4; q++) { bst[q][0] = 3.4e38f; bst[q][1] = 3.4e38f; }

    const int m0 = half * 512;
    for (int m = m0; m < m0 + 512; m += 4) {
        float4 p0 = spts[m];
        float4 p1 = spts[m + 1];
        float4 p2 = spts[m + 2];
        float4 p3 = spts[m + 3];
        #pragma unroll
        for (int q = 0; q < 4; q++) {
            float t0 = fmaf(qz[q], p0.z, fmaf(qy[q], p0.y, fmaf(qx[q], p0.x, p0.w)));
            float t1 = fmaf(qz[q], p1.z, fmaf(qy[q], p1.y, fmaf(qx[q], p1.x, p1.w)));
            float t2 = fmaf(qz[q], p2.z, fmaf(qy[q], p2.y, fmaf(qx[q], p2.x, p2.w)));
            float t3 = fmaf(qz[q], p3.z, fmaf(qy[q], p3.y, fmaf(qx[q], p3.x, p3.w)));
            bst[q][0] = fminf(bst[q][0], fminf(t0, t1));
            bst[q][1] = fminf(bst[q][1], fminf(t2, t3));
        }
    }

    if (half) {
        #pragma unroll
        for (int q = 0; q < 4; q++)
            sup[qt][q] = fminf(bst[q][0], bst[q][1]);
    }
    __syncthreads();

    float acc = 0.0f;
    if (!half) {
        #pragma unroll
        for (int q = 0; q < 4; q++) {
            float lo = fminf(bst[q][0], bst[q][1]);
            acc += qa2[q] + fminf(lo, sup[qt][q]);
        }
    }
    float s = block_sum(acc, sred);
    if (tid == 0) atomicAdd(&g_acc[dir], s);
}

__global__ void final_kernel(float* __restrict__ out) {
    float ch = (g_acc[0] + g_acc[1]) * (1.0f / (float)(BB * NP));
    float l2 = g_acc[2] * (1.0f / (float)(BB * 3 * NP));
    out[0] = 0.1f * ch + 0.9f * l2;
    out[1] = ch;
    out[2] = l2;
}

extern "C" void kernel_launch(void* const* d_in, const int* in_sizes, int n_in,
                              void* d_out, int out_size) {
    const float* pc    = (const float*)d_in[0];
    const float* pc_gt = (const float*)d_in[1];
    const float* lat   = (const float*)d_in[2];
    const float* W1    = (const float*)d_in[3];
    const float* b1    = (const float*)d_in[4];
    const float* W2    = (const float*)d_in[5];
    const float* b2    = (const float*)d_in[6];
    const float* W3    = (const float*)d_in[7];
    const float* b3    = (const float*)d_in[8];
    float* out = (float*)d_out;

    size_t smem = OFF_MISC + (size_t)(384 + 128 + 128 + 384 + 4 + 384 + 384 + 16)
                             * sizeof(float);
    (void)cudaFuncSetAttribute(mlp_kernel,
                               cudaFuncAttributeMaxDynamicSharedMemorySize,
                               (int)smem);

    init_kernel<<<1, 32>>>();
    w1l_kernel<<<BB, 128>>>(lat, W1, b1);
    mlp_kernel<<<MLP_GRID, 256, smem>>>(pc, pc_gt, W2, b2, W1, W3, b3, out + 3);
    chamfer_kernel<<<dim3(BB, 2), 512>>>(pc_gt, out + 3);
    final_kernel<<<1, 1>>>(out);
}